// round 1
// baseline (speedup 1.0000x reference)
#include <cuda_runtime.h>
#include <math.h>

#define Bn   8
#define Gn   1024
#define Mn   8
#define Nn   2048
#define RBFn 50
#define RPAD 52
#define Hn   128
#define Fn   3200
#define Tn   8   // (b,g) pairs per CTA in main kernel

// -------------------- scratch (static device globals; no allocation) -----
__device__ __align__(16) float g_WLp[Hn * 64 * RPAD];   // padded left weights
__device__ __align__(16) float g_WRp[Hn * 64 * RPAD];   // padded right weights
__device__ float g_xc[Bn * Gn * Mn * 3];                // coarse coords
__device__ float g_att[Bn * Gn * Hn];                   // per-(b,g,h) attention

// -------------------- kernel 1: repack weights [H,3200] -> [H][64][52] ---
__global__ void pad_weights_kernel(const float* __restrict__ WL,
                                   const float* __restrict__ WR) {
    int h = blockIdx.x;  // 128 blocks
    for (int e = threadIdx.x; e < 64 * RPAD; e += blockDim.x) {
        int p = e / RPAD;
        int r = e - p * RPAD;
        float vL = 0.f, vR = 0.f;
        if (r < RBFn) {
            vL = WL[h * Fn + p * RBFn + r];
            vR = WR[h * Fn + p * RBFn + r];
        }
        g_WLp[h * 64 * RPAD + e] = vL;
        g_WRp[h * 64 * RPAD + e] = vR;
    }
}

// -------------------- kernel 2: xc[b,g,m,d] = sum_n W_map[g,m,n]*x[b,n,d]
// One CTA per g. x (8*2048*3 floats) staged in smem as xs[bd][2049] (padded
// row -> conflict-free LDS across the 24 bd lanes).
__global__ void __launch_bounds__(192, 1)
xc_kernel(const float* __restrict__ x, const float* __restrict__ Wmap) {
    extern __shared__ float xs[];  // [24][2049]
    int g = blockIdx.x;

    for (int e = threadIdx.x; e < Bn * Nn * 3; e += blockDim.x) {
        int b   = e / (Nn * 3);
        int rem = e - b * (Nn * 3);
        int n   = rem / 3;
        int d   = rem - n * 3;
        xs[(b * 3 + d) * 2049 + n] = x[e];
    }
    __syncthreads();

    int t  = threadIdx.x;       // 192 threads: (m, bd)
    int m  = t / 24;
    int bd = t - m * 24;
    const float* __restrict__ wrow = Wmap + (size_t)(g * Mn + m) * Nn;
    const float* xrow = xs + bd * 2049;

    float a0 = 0.f, a1 = 0.f, a2 = 0.f, a3 = 0.f;
    #pragma unroll 4
    for (int n = 0; n < Nn; n += 4) {
        a0 = fmaf(__ldg(wrow + n + 0), xrow[n + 0], a0);
        a1 = fmaf(__ldg(wrow + n + 1), xrow[n + 1], a1);
        a2 = fmaf(__ldg(wrow + n + 2), xrow[n + 2], a2);
        a3 = fmaf(__ldg(wrow + n + 3), xrow[n + 3], a3);
    }
    float acc = (a0 + a1) + (a2 + a3);

    int b = bd / 3;
    int d = bd - b * 3;
    // layout: g_xc[(b*Gn+g)*24 + m*3 + d]
    g_xc[((b * Gn + g) * Mn + m) * 3 + d] = acc;
}

// -------------------- kernel 3: main fused kernel --------------------
// Each CTA: Tn=8 (b,g) pairs. Phase A: build sm[t][p][r] (+zeros in pad) and
// delta[t][p][d] in smem. Phase B: thread owns h = tid&127 and t-half
// (tid>>7)*4..+4; accumulates wsum[h,p] = sum_r W'[h,p,r]*sm[t,p,r] (float4
// weight LDG, warp-uniform smem broadcast), then left/right[h,d] += wsum*delta.
__global__ void __launch_bounds__(256)
main_kernel(float MU0f, float DMf, float BETAf) {
    extern __shared__ float sh[];
    float* smv = sh;                          // Tn*64*RPAD = 26624 floats
    float* dl  = sh + Tn * 64 * RPAD;         // Tn*64*4   = 2048 floats
    float* xcs = dl + Tn * 64 * 4;            // Tn*24     = 192 floats

    int bg0 = blockIdx.x * Tn;

    for (int e = threadIdx.x; e < Tn * 24; e += blockDim.x)
        xcs[e] = g_xc[bg0 * 24 + e];
    __syncthreads();

    // ---- Phase A: sm + delta ----
    for (int item = threadIdx.x; item < Tn * 64; item += blockDim.x) {
        int t = item >> 6;
        int p = item & 63;
        int i = p >> 3;
        int j = p & 7;
        const float* xt = xcs + t * 24;
        float dx = xt[j * 3 + 0] - xt[i * 3 + 0];
        float dy = xt[j * 3 + 1] - xt[i * 3 + 1];
        float dz = xt[j * 3 + 2] - xt[i * 3 + 2];
        float* drow = dl + (t * 64 + p) * 4;
        drow[0] = dx; drow[1] = dy; drow[2] = dz;

        float dn  = sqrtf(fmaf(dx, dx, fmaf(dy, dy, dz * dz)) + 1e-5f);
        float e_  = __expf(-dn);  // alpha = 1, CUT_LO = 0
        float cut = (dn < 5.0f)
                  ? 0.5f * (__cosf(dn * 0.6283185307179586f) + 1.0f)
                  : 0.0f;
        float dd   = dn + 1e-5f;
        float coef = cut / (dd * dd);

        float* srow = smv + (t * 64 + p) * RPAD;
        #pragma unroll
        for (int r = 0; r < RBFn; r++) {
            float mu = fmaf((float)r, DMf, MU0f);
            float u  = e_ - mu;
            srow[r]  = coef * __expf(-BETAf * u * u);
        }
        srow[50] = 0.f;
        srow[51] = 0.f;
    }
    __syncthreads();

    // ---- Phase B: dual projections (factored) ----
    int h  = threadIdx.x & 127;
    int tg = threadIdx.x >> 7;  // 0 or 1 -> t in [tg*4, tg*4+4)

    const float4* __restrict__ wl = ((const float4*)g_WLp) + h * (64 * RPAD / 4);
    const float4* __restrict__ wr = ((const float4*)g_WRp) + h * (64 * RPAD / 4);

    const float* smbase = smv + tg * 4 * 64 * RPAD;
    const float* dlbase = dl  + tg * 4 * 64 * 4;

    float accL[4][3] = {{0.f}}, accR[4][3] = {{0.f}};

    for (int p = 0; p < 64; p++) {
        float wsL[4] = {0.f, 0.f, 0.f, 0.f};
        float wsR[4] = {0.f, 0.f, 0.f, 0.f};
        #pragma unroll
        for (int q = 0; q < 13; q++) {
            float4 a = __ldg(wl + p * 13 + q);
            float4 c = __ldg(wr + p * 13 + q);
            #pragma unroll
            for (int tt = 0; tt < 4; tt++) {
                // warp-uniform address -> LDS broadcast
                float4 s = *(const float4*)(smbase + tt * (64 * RPAD) + p * RPAD + q * 4);
                wsL[tt] = fmaf(a.x, s.x, wsL[tt]);
                wsL[tt] = fmaf(a.y, s.y, wsL[tt]);
                wsL[tt] = fmaf(a.z, s.z, wsL[tt]);
                wsL[tt] = fmaf(a.w, s.w, wsL[tt]);
                wsR[tt] = fmaf(c.x, s.x, wsR[tt]);
                wsR[tt] = fmaf(c.y, s.y, wsR[tt]);
                wsR[tt] = fmaf(c.z, s.z, wsR[tt]);
                wsR[tt] = fmaf(c.w, s.w, wsR[tt]);
            }
        }
        #pragma unroll
        for (int tt = 0; tt < 4; tt++) {
            const float* dr = dlbase + tt * 256 + p * 4;
            float d0 = dr[0], d1 = dr[1], d2 = dr[2];
            accL[tt][0] = fmaf(wsL[tt], d0, accL[tt][0]);
            accL[tt][1] = fmaf(wsL[tt], d1, accL[tt][1]);
            accL[tt][2] = fmaf(wsL[tt], d2, accL[tt][2]);
            accR[tt][0] = fmaf(wsR[tt], d0, accR[tt][0]);
            accR[tt][1] = fmaf(wsR[tt], d1, accR[tt][1]);
            accR[tt][2] = fmaf(wsR[tt], d2, accR[tt][2]);
        }
    }

    #pragma unroll
    for (int tt = 0; tt < 4; tt++) {
        float att = fmaf(accL[tt][0], accR[tt][0],
                    fmaf(accL[tt][1], accR[tt][1],
                         accL[tt][2] * accR[tt][2])) + 1e-5f;
        g_att[(size_t)(bg0 + tg * 4 + tt) * Hn + h] = att;
    }
}

// -------------------- kernel 4: logsumexp over G + MLP --------------------
__global__ void __launch_bounds__(128)
finalize_kernel(const float* __restrict__ fc1w, const float* __restrict__ fc1b,
                const float* __restrict__ fc2w, const float* __restrict__ fc2b,
                float* __restrict__ out) {
    int b = blockIdx.x;   // 8
    int h = threadIdx.x;  // 128
    const float* col = g_att + (size_t)b * Gn * Hn + h;

    float mx = -3.4e38f;
    #pragma unroll 8
    for (int g = 0; g < Gn; g++) mx = fmaxf(mx, col[g * Hn]);
    float s = 0.f;
    #pragma unroll 8
    for (int g = 0; g < Gn; g++) s += __expf(col[g * Hn] - mx);
    float pooled = mx + logf(s);

    __shared__ float ps[Hn];
    __shared__ float red[Hn];
    ps[h] = pooled;
    __syncthreads();

    float a = fc1b[h];
    #pragma unroll 8
    for (int i = 0; i < Hn; i++) a = fmaf(fc1w[h * Hn + i], ps[i], a);
    float hv = a / (1.f + __expf(-a));  // silu

    red[h] = hv * fc2w[h];
    __syncthreads();
    for (int st = 64; st > 0; st >>= 1) {
        if (h < st) red[h] += red[h + st];
        __syncthreads();
    }
    if (h == 0) out[b] = red[0] + fc2b[0];
}

// -------------------- launcher --------------------
extern "C" void kernel_launch(void* const* d_in, const int* in_sizes, int n_in,
                              void* d_out, int out_size) {
    const float* x    = (const float*)d_in[0];
    const float* Wmap = (const float*)d_in[1];
    const float* WL   = (const float*)d_in[2];
    const float* WR   = (const float*)d_in[3];
    const float* fc1w = (const float*)d_in[4];
    const float* fc1b = (const float*)d_in[5];
    const float* fc2w = (const float*)d_in[6];
    const float* fc2b = (const float*)d_in[7];
    float* out = (float*)d_out;

    // ExpNormalSmearing constants (computed in double, cast to float;
    // matches np.float32 of the float64 expressions in the reference)
    double mu0  = exp(-5.0);
    double dm   = (1.0 - mu0) / 49.0;
    double beta = pow(2.0 / 50.0 * (1.0 - mu0), -2.0);

    const int smem_xc   = 24 * 2049 * (int)sizeof(float);                  // 196704
    const int smem_main = (Tn * 64 * RPAD + Tn * 64 * 4 + Tn * 24) * (int)sizeof(float); // 115456

    cudaFuncSetAttribute(xc_kernel, cudaFuncAttributeMaxDynamicSharedMemorySize, smem_xc);
    cudaFuncSetAttribute(main_kernel, cudaFuncAttributeMaxDynamicSharedMemorySize, smem_main);

    pad_weights_kernel<<<Hn, 256>>>(WL, WR);
    xc_kernel<<<Gn, 192, smem_xc>>>(x, Wmap);
    main_kernel<<<(Bn * Gn) / Tn, 256, smem_main>>>((float)mu0, (float)dm, (float)beta);
    finalize_kernel<<<Bn, 128>>>(fc1w, fc1b, fc2w, fc2b, out);
}

// round 2
// speedup vs baseline: 1.0823x; 1.0823x over previous
#include <cuda_runtime.h>
#include <math.h>

#define Bn   8
#define Gn   1024
#define Mn   8
#define Nn   2048
#define RBFn 50
#define RPAD 52
#define Hn   128
#define Fn   3200
#define Tn   8    // (b,g) pairs per CTA in main kernel
#define XC_ROWS 16   // (g,m) rows per CTA in xc kernel
#define LSE_CH  32   // g-chunks for logsumexp split (32 g each)

// -------------------- scratch (static device globals; no allocation) -----
__device__ __align__(16) float g_WLp[Hn * 64 * RPAD];   // padded left weights
__device__ __align__(16) float g_WRp[Hn * 64 * RPAD];   // padded right weights
__device__ float g_xc[Bn * Gn * Mn * 3];                // coarse coords
__device__ float g_att[Bn * Gn * Hn];                   // per-(b,g,h) attention
__device__ float g_lsem[Bn * LSE_CH * Hn];              // partial lse max
__device__ float g_lses[Bn * LSE_CH * Hn];              // partial lse sum

// -------------------- kernel 1: repack weights [H,3200] -> [H][64][52] ---
__global__ void pad_weights_kernel(const float* __restrict__ WL,
                                   const float* __restrict__ WR) {
    int h = blockIdx.x;  // 128 blocks
    for (int e = threadIdx.x; e < 64 * RPAD; e += blockDim.x) {
        int p = e / RPAD;
        int r = e - p * RPAD;
        float vL = 0.f, vR = 0.f;
        if (r < RBFn) {
            vL = WL[h * Fn + p * RBFn + r];
            vR = WR[h * Fn + p * RBFn + r];
        }
        g_WLp[h * 64 * RPAD + e] = vL;
        g_WRp[h * 64 * RPAD + e] = vR;
    }
}

// -------------------- kernel 2: xc = batched thin GEMM --------------------
// rows = (g,m) in [0,8192), cols c = (b,d) in [0,24).
// Each CTA: 16 rows x 24 cols, 384 threads, one output per thread.
// x staged in smem as xs[n][24] (96B rows -> conflict-free broadcast LDS).
// Wmap read as float4, warp-broadcast (<=2 distinct addrs/warp), L1-served.
__global__ void __launch_bounds__(XC_ROWS * 24, 1)
xc_kernel(const float* __restrict__ x, const float* __restrict__ Wmap) {
    extern __shared__ float xs[];  // [Nn][24] = 196608 bytes

    // stage x: iterate in input order (coalesced reads)
    for (int e = threadIdx.x; e < Bn * Nn * 3; e += XC_ROWS * 24) {
        int b   = e / (Nn * 3);
        int rem = e - b * (Nn * 3);
        int n   = rem / 3;
        int d   = rem - n * 3;
        xs[n * 24 + b * 3 + d] = x[e];
    }
    __syncthreads();

    int row = blockIdx.x * XC_ROWS + threadIdx.x / 24;  // (g,m) row
    int c   = threadIdx.x % 24;                          // (b,d) col

    const float4* __restrict__ wrow =
        reinterpret_cast<const float4*>(Wmap) + (size_t)row * (Nn / 4);

    float a0 = 0.f, a1 = 0.f, a2 = 0.f, a3 = 0.f;
    #pragma unroll 8
    for (int n4 = 0; n4 < Nn / 4; n4++) {
        float4 w = __ldg(wrow + n4);
        const float* xp = xs + n4 * 96 + c;
        a0 = fmaf(w.x, xp[0],  a0);
        a1 = fmaf(w.y, xp[24], a1);
        a2 = fmaf(w.z, xp[48], a2);
        a3 = fmaf(w.w, xp[72], a3);
    }
    float acc = (a0 + a1) + (a2 + a3);

    int b = c / 3;
    int d = c - b * 3;
    // layout matches main kernel read: ((b*Gn+g)*Mn+m)*3+d = (b*8192+row)*3+d
    g_xc[((size_t)b * (Gn * Mn) + row) * 3 + d] = acc;
}

// -------------------- kernel 3: main fused kernel --------------------
__global__ void __launch_bounds__(256)
main_kernel(float MU0f, float DMf, float BETAf) {
    extern __shared__ float sh[];
    float* smv = sh;                          // Tn*64*RPAD = 26624 floats
    float* dl  = sh + Tn * 64 * RPAD;         // Tn*64*4   = 2048 floats
    float* xcs = dl + Tn * 64 * 4;            // Tn*24     = 192 floats

    int bg0 = blockIdx.x * Tn;

    for (int e = threadIdx.x; e < Tn * 24; e += blockDim.x)
        xcs[e] = g_xc[bg0 * 24 + e];
    __syncthreads();

    // ---- Phase A: sm + delta ----
    for (int item = threadIdx.x; item < Tn * 64; item += blockDim.x) {
        int t = item >> 6;
        int p = item & 63;
        int i = p >> 3;
        int j = p & 7;
        const float* xt = xcs + t * 24;
        float dx = xt[j * 3 + 0] - xt[i * 3 + 0];
        float dy = xt[j * 3 + 1] - xt[i * 3 + 1];
        float dz = xt[j * 3 + 2] - xt[i * 3 + 2];
        float* drow = dl + (t * 64 + p) * 4;
        drow[0] = dx; drow[1] = dy; drow[2] = dz;

        float dn  = sqrtf(fmaf(dx, dx, fmaf(dy, dy, dz * dz)) + 1e-5f);
        float e_  = __expf(-dn);  // alpha = 1, CUT_LO = 0
        float cut = (dn < 5.0f)
                  ? 0.5f * (__cosf(dn * 0.6283185307179586f) + 1.0f)
                  : 0.0f;
        float dd   = dn + 1e-5f;
        float coef = cut / (dd * dd);

        float* srow = smv + (t * 64 + p) * RPAD;
        #pragma unroll
        for (int r = 0; r < RBFn; r++) {
            float mu = fmaf((float)r, DMf, MU0f);
            float u  = e_ - mu;
            srow[r]  = coef * __expf(-BETAf * u * u);
        }
        srow[50] = 0.f;
        srow[51] = 0.f;
    }
    __syncthreads();

    // ---- Phase B: dual projections (factored over the 3-vector) ----
    int h  = threadIdx.x & 127;
    int tg = threadIdx.x >> 7;  // 0 or 1 -> t in [tg*4, tg*4+4)

    const float4* __restrict__ wl = ((const float4*)g_WLp) + h * (64 * RPAD / 4);
    const float4* __restrict__ wr = ((const float4*)g_WRp) + h * (64 * RPAD / 4);

    const float* smbase = smv + tg * 4 * 64 * RPAD;
    const float* dlbase = dl  + tg * 4 * 64 * 4;

    float accL[4][3] = {{0.f}}, accR[4][3] = {{0.f}};

    for (int p = 0; p < 64; p++) {
        float wsL[4] = {0.f, 0.f, 0.f, 0.f};
        float wsR[4] = {0.f, 0.f, 0.f, 0.f};
        #pragma unroll
        for (int q = 0; q < 13; q++) {
            float4 a = __ldg(wl + p * 13 + q);
            float4 c = __ldg(wr + p * 13 + q);
            #pragma unroll
            for (int tt = 0; tt < 4; tt++) {
                float4 s = *(const float4*)(smbase + tt * (64 * RPAD) + p * RPAD + q * 4);
                wsL[tt] = fmaf(a.x, s.x, wsL[tt]);
                wsL[tt] = fmaf(a.y, s.y, wsL[tt]);
                wsL[tt] = fmaf(a.z, s.z, wsL[tt]);
                wsL[tt] = fmaf(a.w, s.w, wsL[tt]);
                wsR[tt] = fmaf(c.x, s.x, wsR[tt]);
                wsR[tt] = fmaf(c.y, s.y, wsR[tt]);
                wsR[tt] = fmaf(c.z, s.z, wsR[tt]);
                wsR[tt] = fmaf(c.w, s.w, wsR[tt]);
            }
        }
        #pragma unroll
        for (int tt = 0; tt < 4; tt++) {
            const float* dr = dlbase + tt * 256 + p * 4;
            float d0 = dr[0], d1 = dr[1], d2 = dr[2];
            accL[tt][0] = fmaf(wsL[tt], d0, accL[tt][0]);
            accL[tt][1] = fmaf(wsL[tt], d1, accL[tt][1]);
            accL[tt][2] = fmaf(wsL[tt], d2, accL[tt][2]);
            accR[tt][0] = fmaf(wsR[tt], d0, accR[tt][0]);
            accR[tt][1] = fmaf(wsR[tt], d1, accR[tt][1]);
            accR[tt][2] = fmaf(wsR[tt], d2, accR[tt][2]);
        }
    }

    #pragma unroll
    for (int tt = 0; tt < 4; tt++) {
        float att = fmaf(accL[tt][0], accR[tt][0],
                    fmaf(accL[tt][1], accR[tt][1],
                         accL[tt][2] * accR[tt][2])) + 1e-5f;
        g_att[(size_t)(bg0 + tg * 4 + tt) * Hn + h] = att;
    }
}

// -------------------- kernel 4a: partial logsumexp over g-chunks ---------
// grid (LSE_CH, Bn), block 128. Coalesced 512B row reads of g_att.
__global__ void __launch_bounds__(128)
lse_partial_kernel() {
    int b  = blockIdx.y;
    int ch = blockIdx.x;
    int h  = threadIdx.x;
    const int GPC = Gn / LSE_CH;  // 32 g per chunk
    const float* base = g_att + ((size_t)b * Gn + ch * GPC) * Hn + h;

    float v[GPC];
    #pragma unroll
    for (int i = 0; i < GPC; i++) v[i] = base[(size_t)i * Hn];

    float mx = v[0];
    #pragma unroll
    for (int i = 1; i < GPC; i++) mx = fmaxf(mx, v[i]);
    float s = 0.f;
    #pragma unroll
    for (int i = 0; i < GPC; i++) s += __expf(v[i] - mx);

    g_lsem[(b * LSE_CH + ch) * Hn + h] = mx;
    g_lses[(b * LSE_CH + ch) * Hn + h] = s;
}

// -------------------- kernel 4b: combine + MLP --------------------
__global__ void __launch_bounds__(128)
finalize_kernel(const float* __restrict__ fc1w, const float* __restrict__ fc1b,
                const float* __restrict__ fc2w, const float* __restrict__ fc2b,
                float* __restrict__ out) {
    int b = blockIdx.x;   // 8
    int h = threadIdx.x;  // 128

    float M = -3.4e38f;
    #pragma unroll
    for (int ch = 0; ch < LSE_CH; ch++)
        M = fmaxf(M, g_lsem[(b * LSE_CH + ch) * Hn + h]);
    float S = 0.f;
    #pragma unroll
    for (int ch = 0; ch < LSE_CH; ch++) {
        float m = g_lsem[(b * LSE_CH + ch) * Hn + h];
        float s = g_lses[(b * LSE_CH + ch) * Hn + h];
        S += s * __expf(m - M);
    }
    float pooled = M + logf(S);

    __shared__ float ps[Hn];
    __shared__ float red[Hn];
    ps[h] = pooled;
    __syncthreads();

    float a = fc1b[h];
    #pragma unroll 8
    for (int i = 0; i < Hn; i++) a = fmaf(fc1w[h * Hn + i], ps[i], a);
    float hv = a / (1.f + __expf(-a));  // silu

    red[h] = hv * fc2w[h];
    __syncthreads();
    for (int st = 64; st > 0; st >>= 1) {
        if (h < st) red[h] += red[h + st];
        __syncthreads();
    }
    if (h == 0) out[b] = red[0] + fc2b[0];
}

// -------------------- launcher --------------------
extern "C" void kernel_launch(void* const* d_in, const int* in_sizes, int n_in,
                              void* d_out, int out_size) {
    const float* x    = (const float*)d_in[0];
    const float* Wmap = (const float*)d_in[1];
    const float* WL   = (const float*)d_in[2];
    const float* WR   = (const float*)d_in[3];
    const float* fc1w = (const float*)d_in[4];
    const float* fc1b = (const float*)d_in[5];
    const float* fc2w = (const float*)d_in[6];
    const float* fc2b = (const float*)d_in[7];
    float* out = (float*)d_out;

    double mu0  = exp(-5.0);
    double dm   = (1.0 - mu0) / 49.0;
    double beta = pow(2.0 / 50.0 * (1.0 - mu0), -2.0);

    const int smem_xc   = Nn * 24 * (int)sizeof(float);   // 196608
    const int smem_main = (Tn * 64 * RPAD + Tn * 64 * 4 + Tn * 24) * (int)sizeof(float); // 115456

    cudaFuncSetAttribute(xc_kernel, cudaFuncAttributeMaxDynamicSharedMemorySize, smem_xc);
    cudaFuncSetAttribute(main_kernel, cudaFuncAttributeMaxDynamicSharedMemorySize, smem_main);

    pad_weights_kernel<<<Hn, 256>>>(WL, WR);
    xc_kernel<<<(Gn * Mn) / XC_ROWS, XC_ROWS * 24, smem_xc>>>(x, Wmap);
    main_kernel<<<(Bn * Gn) / Tn, 256, smem_main>>>((float)mu0, (float)dm, (float)beta);
    lse_partial_kernel<<<dim3(LSE_CH, Bn), 128>>>();
    finalize_kernel<<<Bn, 128>>>(fc1w, fc1b, fc2w, fc2b, out);
}

// round 3
// speedup vs baseline: 4.4503x; 4.1120x over previous
#include <cuda_runtime.h>
#include <math.h>

#define Bn   8
#define Gn   1024
#define Mn   8
#define Nn   2048
#define RBFn 50
#define RPAD 52
#define QCH  13   // 13 float4 chunks of r (52 padded)
#define Hn   128
#define Fn   3200
#define Tn   8    // (b,g) pairs per CTA in main kernel
#define XC_ROWS 16
#define LSE_CH  32

// -------------------- scratch (static device globals) --------------------
// transposed+padded weights: [p(64)][q(13)][h(128)][rr(4)]
__device__ __align__(16) float g_WLp[64 * QCH * Hn * 4];
__device__ __align__(16) float g_WRp[64 * QCH * Hn * 4];
__device__ float g_xc[Bn * Gn * Mn * 3];
__device__ float g_att[Bn * Gn * Hn];
__device__ float g_lsem[Bn * LSE_CH * Hn];
__device__ float g_lses[Bn * LSE_CH * Hn];

// ---------- kernel 1: repack weights [H,3200] -> [p][q][h][4] ----------
__global__ void __launch_bounds__(128)
pad_weights_kernel(const float* __restrict__ WL, const float* __restrict__ WR) {
    int pq = blockIdx.x;          // 0..831
    int p  = pq / QCH;
    int q  = pq - p * QCH;
    int h  = threadIdx.x;         // 0..127
    #pragma unroll
    for (int rr = 0; rr < 4; rr++) {
        int r = q * 4 + rr;
        float vL = 0.f, vR = 0.f;
        if (r < RBFn) {
            vL = WL[h * Fn + p * RBFn + r];
            vR = WR[h * Fn + p * RBFn + r];
        }
        int idx = (pq * Hn + h) * 4 + rr;
        g_WLp[idx] = vL;
        g_WRp[idx] = vR;
    }
}

// ---------- kernel 2: xc = batched thin GEMM (unchanged from R2) ----------
__global__ void __launch_bounds__(XC_ROWS * 24, 1)
xc_kernel(const float* __restrict__ x, const float* __restrict__ Wmap) {
    extern __shared__ float xs[];  // [Nn][24]

    for (int e = threadIdx.x; e < Bn * Nn * 3; e += XC_ROWS * 24) {
        int b   = e / (Nn * 3);
        int rem = e - b * (Nn * 3);
        int n   = rem / 3;
        int d   = rem - n * 3;
        xs[n * 24 + b * 3 + d] = x[e];
    }
    __syncthreads();

    int row = blockIdx.x * XC_ROWS + threadIdx.x / 24;
    int c   = threadIdx.x % 24;

    const float4* __restrict__ wrow =
        reinterpret_cast<const float4*>(Wmap) + (size_t)row * (Nn / 4);

    float a0 = 0.f, a1 = 0.f, a2 = 0.f, a3 = 0.f;
    #pragma unroll 8
    for (int n4 = 0; n4 < Nn / 4; n4++) {
        float4 w = __ldg(wrow + n4);
        const float* xp = xs + n4 * 96 + c;
        a0 = fmaf(w.x, xp[0],  a0);
        a1 = fmaf(w.y, xp[24], a1);
        a2 = fmaf(w.z, xp[48], a2);
        a3 = fmaf(w.w, xp[72], a3);
    }
    float acc = (a0 + a1) + (a2 + a3);

    int b = c / 3;
    int d = c - b * 3;
    g_xc[((size_t)b * (Gn * Mn) + row) * 3 + d] = acc;
}

// -------------------- kernel 3: main fused kernel --------------------
// Phase A: build sm[t][p][r] + delta in smem (as before).
// Phase B: thread = (h, p-half). Accumulates ALL 8 t in registers.
// Weights now [pq][h][4] -> LDG.128 is 512B-contiguous per warp (4 wf, not 32).
__global__ void __launch_bounds__(256)
main_kernel(float MU0f, float DMf, float BETAf) {
    extern __shared__ float sh[];
    float* smv = sh;                          // Tn*64*RPAD = 26624 floats
    float* dl  = sh + Tn * 64 * RPAD;         // Tn*64*4
    float* xcs = dl + Tn * 64 * 4;            // Tn*24

    int bg0 = blockIdx.x * Tn;

    for (int e = threadIdx.x; e < Tn * 24; e += blockDim.x)
        xcs[e] = g_xc[bg0 * 24 + e];
    __syncthreads();

    // ---- Phase A ----
    for (int item = threadIdx.x; item < Tn * 64; item += blockDim.x) {
        int t = item >> 6;
        int p = item & 63;
        int i = p >> 3;
        int j = p & 7;
        const float* xt = xcs + t * 24;
        float dx = xt[j * 3 + 0] - xt[i * 3 + 0];
        float dy = xt[j * 3 + 1] - xt[i * 3 + 1];
        float dz = xt[j * 3 + 2] - xt[i * 3 + 2];
        float* drow = dl + (t * 64 + p) * 4;
        drow[0] = dx; drow[1] = dy; drow[2] = dz;

        float dn  = sqrtf(fmaf(dx, dx, fmaf(dy, dy, dz * dz)) + 1e-5f);
        float e_  = __expf(-dn);
        float cut = (dn < 5.0f)
                  ? 0.5f * (__cosf(dn * 0.6283185307179586f) + 1.0f)
                  : 0.0f;
        float dd   = dn + 1e-5f;
        float coef = cut / (dd * dd);

        float* srow = smv + (t * 64 + p) * RPAD;
        #pragma unroll
        for (int r = 0; r < RBFn; r++) {
            float mu = fmaf((float)r, DMf, MU0f);
            float u  = e_ - mu;
            srow[r]  = coef * __expf(-BETAf * u * u);
        }
        srow[50] = 0.f;
        srow[51] = 0.f;
    }
    __syncthreads();

    // ---- Phase B ----
    int h  = threadIdx.x & 127;
    int ph = threadIdx.x >> 7;      // p-half: p in [ph*32, ph*32+32)

    const float4* __restrict__ wl = ((const float4*)g_WLp) + h;
    const float4* __restrict__ wr = ((const float4*)g_WRp) + h;

    float accL[Tn][3] = {{0.f}}, accR[Tn][3] = {{0.f}};

    int p0 = ph * 32;
    for (int p = p0; p < p0 + 32; p++) {
        float wsL[Tn] = {0.f}, wsR[Tn] = {0.f};
        #pragma unroll
        for (int q = 0; q < QCH; q++) {
            float4 a = __ldg(wl + (size_t)(p * QCH + q) * Hn);
            float4 c = __ldg(wr + (size_t)(p * QCH + q) * Hn);
            #pragma unroll
            for (int tt = 0; tt < Tn; tt++) {
                float4 s = *(const float4*)(smv + tt * (64 * RPAD) + p * RPAD + q * 4);
                wsL[tt] = fmaf(a.x, s.x, wsL[tt]);
                wsL[tt] = fmaf(a.y, s.y, wsL[tt]);
                wsL[tt] = fmaf(a.z, s.z, wsL[tt]);
                wsL[tt] = fmaf(a.w, s.w, wsL[tt]);
                wsR[tt] = fmaf(c.x, s.x, wsR[tt]);
                wsR[tt] = fmaf(c.y, s.y, wsR[tt]);
                wsR[tt] = fmaf(c.z, s.z, wsR[tt]);
                wsR[tt] = fmaf(c.w, s.w, wsR[tt]);
            }
        }
        #pragma unroll
        for (int tt = 0; tt < Tn; tt++) {
            const float* dr = dl + tt * 256 + p * 4;
            float d0 = dr[0], d1 = dr[1], d2 = dr[2];
            accL[tt][0] = fmaf(wsL[tt], d0, accL[tt][0]);
            accL[tt][1] = fmaf(wsL[tt], d1, accL[tt][1]);
            accL[tt][2] = fmaf(wsL[tt], d2, accL[tt][2]);
            accR[tt][0] = fmaf(wsR[tt], d0, accR[tt][0]);
            accR[tt][1] = fmaf(wsR[tt], d1, accR[tt][1]);
            accR[tt][2] = fmaf(wsR[tt], d2, accR[tt][2]);
        }
    }

    // ---- cross-half reduction (reuse smv; 49-stride to dodge conflicts) ----
    __syncthreads();
    float* red = smv;  // 128*49 = 6272 floats << 26624
    if (ph == 1) {
        float* r0 = red + h * 49;
        #pragma unroll
        for (int tt = 0; tt < Tn; tt++) {
            #pragma unroll
            for (int d = 0; d < 3; d++) {
                r0[tt * 6 + d]     = accL[tt][d];
                r0[tt * 6 + 3 + d] = accR[tt][d];
            }
        }
    }
    __syncthreads();
    if (ph == 0) {
        const float* r0 = red + h * 49;
        #pragma unroll
        for (int tt = 0; tt < Tn; tt++) {
            float L0 = accL[tt][0] + r0[tt * 6 + 0];
            float L1 = accL[tt][1] + r0[tt * 6 + 1];
            float L2 = accL[tt][2] + r0[tt * 6 + 2];
            float R0 = accR[tt][0] + r0[tt * 6 + 3];
            float R1 = accR[tt][1] + r0[tt * 6 + 4];
            float R2 = accR[tt][2] + r0[tt * 6 + 5];
            float att = fmaf(L0, R0, fmaf(L1, R1, L2 * R2)) + 1e-5f;
            g_att[(size_t)(bg0 + tt) * Hn + h] = att;
        }
    }
}

// ---------- kernel 4a: partial logsumexp ----------
__global__ void __launch_bounds__(128)
lse_partial_kernel() {
    int b  = blockIdx.y;
    int ch = blockIdx.x;
    int h  = threadIdx.x;
    const int GPC = Gn / LSE_CH;
    const float* base = g_att + ((size_t)b * Gn + ch * GPC) * Hn + h;

    float v[GPC];
    #pragma unroll
    for (int i = 0; i < GPC; i++) v[i] = base[(size_t)i * Hn];

    float mx = v[0];
    #pragma unroll
    for (int i = 1; i < GPC; i++) mx = fmaxf(mx, v[i]);
    float s = 0.f;
    #pragma unroll
    for (int i = 0; i < GPC; i++) s += __expf(v[i] - mx);

    g_lsem[(b * LSE_CH + ch) * Hn + h] = mx;
    g_lses[(b * LSE_CH + ch) * Hn + h] = s;
}

// ---------- kernel 4b: combine + MLP ----------
__global__ void __launch_bounds__(128)
finalize_kernel(const float* __restrict__ fc1w, const float* __restrict__ fc1b,
                const float* __restrict__ fc2w, const float* __restrict__ fc2b,
                float* __restrict__ out) {
    int b = blockIdx.x;
    int h = threadIdx.x;

    float M = -3.4e38f;
    #pragma unroll
    for (int ch = 0; ch < LSE_CH; ch++)
        M = fmaxf(M, g_lsem[(b * LSE_CH + ch) * Hn + h]);
    float S = 0.f;
    #pragma unroll
    for (int ch = 0; ch < LSE_CH; ch++) {
        float m = g_lsem[(b * LSE_CH + ch) * Hn + h];
        float s = g_lses[(b * LSE_CH + ch) * Hn + h];
        S += s * __expf(m - M);
    }
    float pooled = M + logf(S);

    __shared__ float ps[Hn];
    __shared__ float red[Hn];
    ps[h] = pooled;
    __syncthreads();

    float a = fc1b[h];
    #pragma unroll 8
    for (int i = 0; i < Hn; i++) a = fmaf(fc1w[h * Hn + i], ps[i], a);
    float hv = a / (1.f + __expf(-a));

    red[h] = hv * fc2w[h];
    __syncthreads();
    for (int st = 64; st > 0; st >>= 1) {
        if (h < st) red[h] += red[h + st];
        __syncthreads();
    }
    if (h == 0) out[b] = red[0] + fc2b[0];
}

// -------------------- launcher --------------------
extern "C" void kernel_launch(void* const* d_in, const int* in_sizes, int n_in,
                              void* d_out, int out_size) {
    const float* x    = (const float*)d_in[0];
    const float* Wmap = (const float*)d_in[1];
    const float* WL   = (const float*)d_in[2];
    const float* WR   = (const float*)d_in[3];
    const float* fc1w = (const float*)d_in[4];
    const float* fc1b = (const float*)d_in[5];
    const float* fc2w = (const float*)d_in[6];
    const float* fc2b = (const float*)d_in[7];
    float* out = (float*)d_out;

    double mu0  = exp(-5.0);
    double dm   = (1.0 - mu0) / 49.0;
    double beta = pow(2.0 / 50.0 * (1.0 - mu0), -2.0);

    const int smem_xc   = Nn * 24 * (int)sizeof(float);
    const int smem_main = (Tn * 64 * RPAD + Tn * 64 * 4 + Tn * 24) * (int)sizeof(float);

    cudaFuncSetAttribute(xc_kernel, cudaFuncAttributeMaxDynamicSharedMemorySize, smem_xc);
    cudaFuncSetAttribute(main_kernel, cudaFuncAttributeMaxDynamicSharedMemorySize, smem_main);

    pad_weights_kernel<<<64 * QCH, 128>>>(WL, WR);
    xc_kernel<<<(Gn * Mn) / XC_ROWS, XC_ROWS * 24, smem_xc>>>(x, Wmap);
    main_kernel<<<(Bn * Gn) / Tn, 256, smem_main>>>((float)mu0, (float)dm, (float)beta);
    lse_partial_kernel<<<dim3(LSE_CH, Bn), 128>>>();
    finalize_kernel<<<Bn, 128>>>(fc1w, fc1b, fc2w, fc2b, out);
}

// round 4
// speedup vs baseline: 7.6802x; 1.7257x over previous
#include <cuda_runtime.h>
#include <math.h>

#define Bn   8
#define Gn   1024
#define Mn   8
#define Nn   2048
#define RBFn 50
#define RPAD 52
#define QCH  13    // 13 float4 chunks of r
#define NPAIR 28   // i<j pairs of 8 particles
#define Hn   128
#define Fn   3200
#define Tn   8     // (b,g) pairs per CTA in main kernel
#define XC_ROWS 16
#define LSE_CH  32

__constant__ int c_pi[NPAIR] = {0,0,0,0,0,0,0, 1,1,1,1,1,1, 2,2,2,2,2, 3,3,3,3, 4,4,4, 5,5, 6};
__constant__ int c_pj[NPAIR] = {1,2,3,4,5,6,7, 2,3,4,5,6,7, 3,4,5,6,7, 4,5,6,7, 5,6,7, 6,7, 7};

// -------------------- scratch (static device globals) --------------------
// folded antisymmetric weights: [pair(28)][q(13)][h(128)][rr(4)]
__device__ __align__(16) float g_WLp[NPAIR * QCH * Hn * 4];
__device__ __align__(16) float g_WRp[NPAIR * QCH * Hn * 4];
__device__ float g_xc[Bn * Gn * Mn * 3];
__device__ float g_att[Bn * Gn * Hn];
__device__ float g_lsem[Bn * LSE_CH * Hn];
__device__ float g_lses[Bn * LSE_CH * Hn];

// ---------- kernel 1: fold + repack weights ----------
// W~[h, (i<j), r] = W[h, (i*8+j)*50 + r] - W[h, (j*8+i)*50 + r]
__global__ void __launch_bounds__(128)
pad_weights_kernel(const float* __restrict__ WL, const float* __restrict__ WR) {
    int kq = blockIdx.x;              // 0..363
    int k  = kq / QCH;
    int q  = kq - k * QCH;
    int h  = threadIdx.x;
    int i  = c_pi[k], j = c_pj[k];
    #pragma unroll
    for (int rr = 0; rr < 4; rr++) {
        int r = q * 4 + rr;
        float vL = 0.f, vR = 0.f;
        if (r < RBFn) {
            int fij = (i * Mn + j) * RBFn + r;
            int fji = (j * Mn + i) * RBFn + r;
            vL = WL[h * Fn + fij] - WL[h * Fn + fji];
            vR = WR[h * Fn + fij] - WR[h * Fn + fji];
        }
        int idx = (kq * Hn + h) * 4 + rr;
        g_WLp[idx] = vL;
        g_WRp[idx] = vR;
    }
}

// ---------- kernel 2: xc = batched thin GEMM ----------
__global__ void __launch_bounds__(XC_ROWS * 24, 1)
xc_kernel(const float* __restrict__ x, const float* __restrict__ Wmap) {
    extern __shared__ float xs[];  // [Nn][24]

    for (int e = threadIdx.x; e < Bn * Nn * 3; e += XC_ROWS * 24) {
        int b   = e / (Nn * 3);
        int rem = e - b * (Nn * 3);
        int n   = rem / 3;
        int d   = rem - n * 3;
        xs[n * 24 + b * 3 + d] = x[e];
    }
    __syncthreads();

    int row = blockIdx.x * XC_ROWS + threadIdx.x / 24;
    int c   = threadIdx.x % 24;

    const float4* __restrict__ wrow =
        reinterpret_cast<const float4*>(Wmap) + (size_t)row * (Nn / 4);

    float a0 = 0.f, a1 = 0.f, a2 = 0.f, a3 = 0.f;
    #pragma unroll 8
    for (int n4 = 0; n4 < Nn / 4; n4++) {
        float4 w = __ldg(wrow + n4);
        const float* xp = xs + n4 * 96 + c;
        a0 = fmaf(w.x, xp[0],  a0);
        a1 = fmaf(w.y, xp[24], a1);
        a2 = fmaf(w.z, xp[48], a2);
        a3 = fmaf(w.w, xp[72], a3);
    }
    float acc = (a0 + a1) + (a2 + a3);

    int b = c / 3;
    int d = c - b * 3;
    g_xc[((size_t)b * (Gn * Mn) + row) * 3 + d] = acc;
}

// -------------------- kernel 3: main fused kernel (28-pair form) ----------
__global__ void __launch_bounds__(256)
main_kernel(float MU0f, float DMf, float BETAf) {
    extern __shared__ float sh[];
    float* smv = sh;                              // Tn*28*RPAD = 11648 floats
    float* dl  = sh + Tn * NPAIR * RPAD;          // Tn*28*4   = 896
    float* xcs = dl + Tn * NPAIR * 4;             // Tn*24     = 192

    int bg0 = blockIdx.x * Tn;

    for (int e = threadIdx.x; e < Tn * 24; e += blockDim.x)
        xcs[e] = g_xc[bg0 * 24 + e];
    __syncthreads();

    // ---- Phase A: sm + delta on the 28 i<j pairs ----
    if (threadIdx.x < Tn * NPAIR) {
        int t = threadIdx.x / NPAIR;
        int k = threadIdx.x - t * NPAIR;
        int i = c_pi[k], j = c_pj[k];
        const float* xt = xcs + t * 24;
        float dx = xt[j * 3 + 0] - xt[i * 3 + 0];
        float dy = xt[j * 3 + 1] - xt[i * 3 + 1];
        float dz = xt[j * 3 + 2] - xt[i * 3 + 2];
        float* drow = dl + (t * NPAIR + k) * 4;
        drow[0] = dx; drow[1] = dy; drow[2] = dz;

        float dn  = sqrtf(fmaf(dx, dx, fmaf(dy, dy, dz * dz)) + 1e-5f);
        float e_  = __expf(-dn);
        float cut = (dn < 5.0f)
                  ? 0.5f * (__cosf(dn * 0.6283185307179586f) + 1.0f)
                  : 0.0f;
        float dd   = dn + 1e-5f;
        float coef = cut / (dd * dd);

        float* srow = smv + (t * NPAIR + k) * RPAD;
        #pragma unroll
        for (int r = 0; r < RBFn; r++) {
            float mu = fmaf((float)r, DMf, MU0f);
            float u  = e_ - mu;
            srow[r]  = coef * __expf(-BETAf * u * u);
        }
        srow[50] = 0.f;
        srow[51] = 0.f;
    }
    __syncthreads();

    // ---- Phase B: dual projections over 28 pairs, split 14/14 ----
    int h  = threadIdx.x & 127;
    int ph = threadIdx.x >> 7;        // pair-half

    const float4* __restrict__ wl = ((const float4*)g_WLp) + h;
    const float4* __restrict__ wr = ((const float4*)g_WRp) + h;

    float accL[Tn][3] = {{0.f}}, accR[Tn][3] = {{0.f}};

    int k0 = ph * (NPAIR / 2);
    for (int k = k0; k < k0 + NPAIR / 2; k++) {
        float wsL[Tn] = {0.f}, wsR[Tn] = {0.f};
        #pragma unroll
        for (int q = 0; q < QCH; q++) {
            float4 a = __ldg(wl + (size_t)(k * QCH + q) * Hn);
            float4 c = __ldg(wr + (size_t)(k * QCH + q) * Hn);
            #pragma unroll
            for (int tt = 0; tt < Tn; tt++) {
                float4 s = *(const float4*)(smv + (tt * NPAIR + k) * RPAD + q * 4);
                wsL[tt] = fmaf(a.x, s.x, wsL[tt]);
                wsL[tt] = fmaf(a.y, s.y, wsL[tt]);
                wsL[tt] = fmaf(a.z, s.z, wsL[tt]);
                wsL[tt] = fmaf(a.w, s.w, wsL[tt]);
                wsR[tt] = fmaf(c.x, s.x, wsR[tt]);
                wsR[tt] = fmaf(c.y, s.y, wsR[tt]);
                wsR[tt] = fmaf(c.z, s.z, wsR[tt]);
                wsR[tt] = fmaf(c.w, s.w, wsR[tt]);
            }
        }
        #pragma unroll
        for (int tt = 0; tt < Tn; tt++) {
            const float* dr = dl + (tt * NPAIR + k) * 4;
            float d0 = dr[0], d1 = dr[1], d2 = dr[2];
            accL[tt][0] = fmaf(wsL[tt], d0, accL[tt][0]);
            accL[tt][1] = fmaf(wsL[tt], d1, accL[tt][1]);
            accL[tt][2] = fmaf(wsL[tt], d2, accL[tt][2]);
            accR[tt][0] = fmaf(wsR[tt], d0, accR[tt][0]);
            accR[tt][1] = fmaf(wsR[tt], d1, accR[tt][1]);
            accR[tt][2] = fmaf(wsR[tt], d2, accR[tt][2]);
        }
    }

    // ---- cross-half reduction (reuse smv) ----
    __syncthreads();
    float* red = smv;   // 128*49 = 6272 floats <= 11648
    if (ph == 1) {
        float* r0 = red + h * 49;
        #pragma unroll
        for (int tt = 0; tt < Tn; tt++) {
            #pragma unroll
            for (int d = 0; d < 3; d++) {
                r0[tt * 6 + d]     = accL[tt][d];
                r0[tt * 6 + 3 + d] = accR[tt][d];
            }
        }
    }
    __syncthreads();
    if (ph == 0) {
        const float* r0 = red + h * 49;
        #pragma unroll
        for (int tt = 0; tt < Tn; tt++) {
            float L0 = accL[tt][0] + r0[tt * 6 + 0];
            float L1 = accL[tt][1] + r0[tt * 6 + 1];
            float L2 = accL[tt][2] + r0[tt * 6 + 2];
            float R0 = accR[tt][0] + r0[tt * 6 + 3];
            float R1 = accR[tt][1] + r0[tt * 6 + 4];
            float R2 = accR[tt][2] + r0[tt * 6 + 5];
            float att = fmaf(L0, R0, fmaf(L1, R1, L2 * R2)) + 1e-5f;
            g_att[(size_t)(bg0 + tt) * Hn + h] = att;
        }
    }
}

// ---------- kernel 4a: partial logsumexp ----------
__global__ void __launch_bounds__(128)
lse_partial_kernel() {
    int b  = blockIdx.y;
    int ch = blockIdx.x;
    int h  = threadIdx.x;
    const int GPC = Gn / LSE_CH;
    const float* base = g_att + ((size_t)b * Gn + ch * GPC) * Hn + h;

    float v[GPC];
    #pragma unroll
    for (int i = 0; i < GPC; i++) v[i] = base[(size_t)i * Hn];

    float mx = v[0];
    #pragma unroll
    for (int i = 1; i < GPC; i++) mx = fmaxf(mx, v[i]);
    float s = 0.f;
    #pragma unroll
    for (int i = 0; i < GPC; i++) s += __expf(v[i] - mx);

    g_lsem[(b * LSE_CH + ch) * Hn + h] = mx;
    g_lses[(b * LSE_CH + ch) * Hn + h] = s;
}

// ---------- kernel 4b: combine + MLP ----------
__global__ void __launch_bounds__(128)
finalize_kernel(const float* __restrict__ fc1w, const float* __restrict__ fc1b,
                const float* __restrict__ fc2w, const float* __restrict__ fc2b,
                float* __restrict__ out) {
    int b = blockIdx.x;
    int h = threadIdx.x;

    float M = -3.4e38f;
    #pragma unroll
    for (int ch = 0; ch < LSE_CH; ch++)
        M = fmaxf(M, g_lsem[(b * LSE_CH + ch) * Hn + h]);
    float S = 0.f;
    #pragma unroll
    for (int ch = 0; ch < LSE_CH; ch++) {
        float m = g_lsem[(b * LSE_CH + ch) * Hn + h];
        float s = g_lses[(b * LSE_CH + ch) * Hn + h];
        S += s * __expf(m - M);
    }
    float pooled = M + logf(S);

    __shared__ float ps[Hn];
    __shared__ float red[Hn];
    ps[h] = pooled;
    __syncthreads();

    float a = fc1b[h];
    #pragma unroll 8
    for (int i = 0; i < Hn; i++) a = fmaf(fc1w[h * Hn + i], ps[i], a);
    float hv = a / (1.f + __expf(-a));

    red[h] = hv * fc2w[h];
    __syncthreads();
    for (int st = 64; st > 0; st >>= 1) {
        if (h < st) red[h] += red[h + st];
        __syncthreads();
    }
    if (h == 0) out[b] = red[0] + fc2b[0];
}

// -------------------- launcher --------------------
extern "C" void kernel_launch(void* const* d_in, const int* in_sizes, int n_in,
                              void* d_out, int out_size) {
    const float* x    = (const float*)d_in[0];
    const float* Wmap = (const float*)d_in[1];
    const float* WL   = (const float*)d_in[2];
    const float* WR   = (const float*)d_in[3];
    const float* fc1w = (const float*)d_in[4];
    const float* fc1b = (const float*)d_in[5];
    const float* fc2w = (const float*)d_in[6];
    const float* fc2b = (const float*)d_in[7];
    float* out = (float*)d_out;

    double mu0  = exp(-5.0);
    double dm   = (1.0 - mu0) / 49.0;
    double beta = pow(2.0 / 50.0 * (1.0 - mu0), -2.0);

    const int smem_xc   = Nn * 24 * (int)sizeof(float);
    const int smem_main = (Tn * NPAIR * RPAD + Tn * NPAIR * 4 + Tn * 24) * (int)sizeof(float);

    cudaFuncSetAttribute(xc_kernel, cudaFuncAttributeMaxDynamicSharedMemorySize, smem_xc);
    cudaFuncSetAttribute(main_kernel, cudaFuncAttributeMaxDynamicSharedMemorySize, smem_main);

    pad_weights_kernel<<<NPAIR * QCH, 128>>>(WL, WR);
    xc_kernel<<<(Gn * Mn) / XC_ROWS, XC_ROWS * 24, smem_xc>>>(x, Wmap);
    main_kernel<<<(Bn * Gn) / Tn, 256, smem_main>>>((float)mu0, (float)dm, (float)beta);
    lse_partial_kernel<<<dim3(LSE_CH, Bn), 128>>>();
    finalize_kernel<<<Bn, 128>>>(fc1w, fc1b, fc2w, fc2b, out);
}

// round 5
// speedup vs baseline: 10.1974x; 1.3278x over previous
#include <cuda_runtime.h>
#include <math.h>

#define Bn   8
#define Gn   1024
#define Mn   8
#define Nn   2048
#define RBFn 50
#define QCH  13     // 13 float4 chunks of r (52 padded)
#define NPAIR 28    // i<j pairs of 8 particles
#define Hn   128
#define Fn   3200
#define Tn   8      // (b,g) pairs per CTA in main kernel
#define KROW 424    // smv row stride per k: 53*8 floats
#define XC_ROWS 32
#define LSE_CH  32

// f32x2 packed math helpers
#define FMA2(d, a, b, c) \
    asm("fma.rn.f32x2 %0, %1, %2, %3;" : "=l"(d) : "l"(a), "l"(b), "l"(c))
#define PK2(d, x) \
    asm("mov.b64 %0, {%1, %1};" : "=l"(d) : "f"(x))
#define UNPK2(lo, hi, v) \
    asm("mov.b64 {%0, %1}, %2;" : "=f"(lo), "=f"(hi) : "l"(v))

__constant__ int c_pi[NPAIR] = {0,0,0,0,0,0,0, 1,1,1,1,1,1, 2,2,2,2,2, 3,3,3,3, 4,4,4, 5,5, 6};
__constant__ int c_pj[NPAIR] = {1,2,3,4,5,6,7, 2,3,4,5,6,7, 3,4,5,6,7, 4,5,6,7, 5,6,7, 6,7, 7};

// -------------------- scratch (static device globals) --------------------
// folded antisymmetric weights: [pair(28)][q(13)][h(128)][rr(4)]
__device__ __align__(16) float g_WLp[NPAIR * QCH * Hn * 4];
__device__ __align__(16) float g_WRp[NPAIR * QCH * Hn * 4];
__device__ float g_xc[Bn * Gn * Mn * 3];
__device__ float g_att[Bn * Gn * Hn];
__device__ float g_lsem[Bn * LSE_CH * Hn];
__device__ float g_lses[Bn * LSE_CH * Hn];

// ---------- kernel 1: fold + repack weights ----------
__global__ void __launch_bounds__(128)
pad_weights_kernel(const float* __restrict__ WL, const float* __restrict__ WR) {
    int kq = blockIdx.x;              // 0..363
    int k  = kq / QCH;
    int q  = kq - k * QCH;
    int h  = threadIdx.x;
    int i  = c_pi[k], j = c_pj[k];
    #pragma unroll
    for (int rr = 0; rr < 4; rr++) {
        int r = q * 4 + rr;
        float vL = 0.f, vR = 0.f;
        if (r < RBFn) {
            int fij = (i * Mn + j) * RBFn + r;
            int fji = (j * Mn + i) * RBFn + r;
            vL = WL[h * Fn + fij] - WL[h * Fn + fji];
            vR = WR[h * Fn + fij] - WR[h * Fn + fji];
        }
        int idx = (kq * Hn + h) * 4 + rr;
        g_WLp[idx] = vL;
        g_WRp[idx] = vR;
    }
}

// ---------- kernel 2: xc = batched thin GEMM ----------
__global__ void __launch_bounds__(XC_ROWS * 24, 1)
xc_kernel(const float* __restrict__ x, const float* __restrict__ Wmap) {
    extern __shared__ float xs[];  // [Nn][24]

    for (int e = threadIdx.x; e < Bn * Nn * 3; e += XC_ROWS * 24) {
        int b   = e / (Nn * 3);
        int rem = e - b * (Nn * 3);
        int n   = rem / 3;
        int d   = rem - n * 3;
        xs[n * 24 + b * 3 + d] = x[e];
    }
    __syncthreads();

    int row = blockIdx.x * XC_ROWS + threadIdx.x / 24;
    int c   = threadIdx.x % 24;

    const float4* __restrict__ wrow =
        reinterpret_cast<const float4*>(Wmap) + (size_t)row * (Nn / 4);

    float a0 = 0.f, a1 = 0.f, a2 = 0.f, a3 = 0.f;
    #pragma unroll 8
    for (int n4 = 0; n4 < Nn / 4; n4++) {
        float4 w = __ldg(wrow + n4);
        const float* xp = xs + n4 * 96 + c;
        a0 = fmaf(w.x, xp[0],  a0);
        a1 = fmaf(w.y, xp[24], a1);
        a2 = fmaf(w.z, xp[48], a2);
        a3 = fmaf(w.w, xp[72], a3);
    }
    float acc = (a0 + a1) + (a2 + a3);

    int b = c / 3;
    int d = c - b * 3;
    g_xc[((size_t)b * (Gn * Mn) + row) * 3 + d] = acc;
}

// -------------------- kernel 3: main fused kernel (f32x2 Phase B) ---------
// smem: smv [28][53][8] (k, r, t) row-stride 424; dl [28][3][8]; xcs [192].
__global__ void __launch_bounds__(256, 2)
main_kernel(float MU0f, float DMf, float BETAf) {
    extern __shared__ float sh[];
    float* smv = sh;                          // 28*424 = 11872 floats
    float* dl  = sh + NPAIR * KROW;           // 28*24  = 672
    float* xcs = dl + NPAIR * 24;             // 192

    int bg0 = blockIdx.x * Tn;

    for (int e = threadIdx.x; e < Tn * 24; e += blockDim.x)
        xcs[e] = g_xc[bg0 * 24 + e];
    __syncthreads();

    // ---- Phase A: thread = (k, t); conflict-free strided stores ----
    if (threadIdx.x < Tn * NPAIR) {
        int k = threadIdx.x >> 3;
        int t = threadIdx.x & 7;
        int i = c_pi[k], j = c_pj[k];
        const float* xt = xcs + t * 24;
        float dx = xt[j * 3 + 0] - xt[i * 3 + 0];
        float dy = xt[j * 3 + 1] - xt[i * 3 + 1];
        float dz = xt[j * 3 + 2] - xt[i * 3 + 2];
        float* drow = dl + k * 24 + t;
        drow[0]  = dx;
        drow[8]  = dy;
        drow[16] = dz;

        float dn  = sqrtf(fmaf(dx, dx, fmaf(dy, dy, dz * dz)) + 1e-5f);
        float e_  = __expf(-dn);
        float cut = (dn < 5.0f)
                  ? 0.5f * (__cosf(dn * 0.6283185307179586f) + 1.0f)
                  : 0.0f;
        float dd   = dn + 1e-5f;
        float coef = cut / (dd * dd);

        float* srow = smv + k * KROW + t;
        #pragma unroll
        for (int r = 0; r < RBFn; r++) {
            float mu = fmaf((float)r, DMf, MU0f);
            float u  = e_ - mu;
            srow[r * 8] = coef * __expf(-BETAf * u * u);
        }
        srow[50 * 8] = 0.f;
        srow[51 * 8] = 0.f;
    }
    __syncthreads();

    // ---- Phase B: f32x2 dual projections over 28 pairs, split 14/14 ----
    int h  = threadIdx.x & 127;
    int ph = threadIdx.x >> 7;

    const float4* __restrict__ wl = ((const float4*)g_WLp) + h;
    const float4* __restrict__ wr = ((const float4*)g_WRp) + h;

    unsigned long long acc2L[4][3] = {{0ull}}, acc2R[4][3] = {{0ull}};

    int k0 = ph * (NPAIR / 2);
    #pragma unroll 2
    for (int k = k0; k < k0 + NPAIR / 2; k++) {
        unsigned long long ws2L[4] = {0ull, 0ull, 0ull, 0ull};
        unsigned long long ws2R[4] = {0ull, 0ull, 0ull, 0ull};
        const float* sk = smv + k * KROW;

        #pragma unroll
        for (int q = 0; q < QCH; q++) {
            float4 a = __ldg(wl + (size_t)(k * QCH + q) * Hn);
            float4 c = __ldg(wr + (size_t)(k * QCH + q) * Hn);

            #define DO_RR(RR, AV, CV)                                          \
            {                                                                  \
                const ulonglong2* sp =                                         \
                    (const ulonglong2*)(sk + (q * 4 + (RR)) * 8);              \
                ulonglong2 s01 = sp[0];                                        \
                ulonglong2 s23 = sp[1];                                        \
                unsigned long long a2, c2;                                     \
                PK2(a2, (AV)); PK2(c2, (CV));                                  \
                FMA2(ws2L[0], a2, s01.x, ws2L[0]);                             \
                FMA2(ws2L[1], a2, s01.y, ws2L[1]);                             \
                FMA2(ws2L[2], a2, s23.x, ws2L[2]);                             \
                FMA2(ws2L[3], a2, s23.y, ws2L[3]);                             \
                FMA2(ws2R[0], c2, s01.x, ws2R[0]);                             \
                FMA2(ws2R[1], c2, s01.y, ws2R[1]);                             \
                FMA2(ws2R[2], c2, s23.x, ws2R[2]);                             \
                FMA2(ws2R[3], c2, s23.y, ws2R[3]);                             \
            }
            DO_RR(0, a.x, c.x)
            DO_RR(1, a.y, c.y)
            DO_RR(2, a.z, c.z)
            DO_RR(3, a.w, c.w)
            #undef DO_RR
        }

        // epilogue: acc += ws * delta (delta packed per d)
        const ulonglong2* dp = ((const ulonglong2*)(dl + k * 24));
        #pragma unroll
        for (int d = 0; d < 3; d++) {
            ulonglong2 d01 = dp[d * 2 + 0];
            ulonglong2 d23 = dp[d * 2 + 1];
            FMA2(acc2L[0][d], ws2L[0], d01.x, acc2L[0][d]);
            FMA2(acc2L[1][d], ws2L[1], d01.y, acc2L[1][d]);
            FMA2(acc2L[2][d], ws2L[2], d23.x, acc2L[2][d]);
            FMA2(acc2L[3][d], ws2L[3], d23.y, acc2L[3][d]);
            FMA2(acc2R[0][d], ws2R[0], d01.x, acc2R[0][d]);
            FMA2(acc2R[1][d], ws2R[1], d01.y, acc2R[1][d]);
            FMA2(acc2R[2][d], ws2R[2], d23.x, acc2R[2][d]);
            FMA2(acc2R[3][d], ws2R[3], d23.y, acc2R[3][d]);
        }
    }

    // ---- cross-half reduction (reuse smv) ----
    __syncthreads();
    float* red = smv;   // 128*49 = 6272 floats <= 11872
    if (ph == 1) {
        float* r0 = red + h * 49;
        #pragma unroll
        for (int u = 0; u < 4; u++) {
            #pragma unroll
            for (int d = 0; d < 3; d++) {
                float lo, hi;
                UNPK2(lo, hi, acc2L[u][d]);
                r0[(2 * u) * 6 + d]     = lo;
                r0[(2 * u + 1) * 6 + d] = hi;
                UNPK2(lo, hi, acc2R[u][d]);
                r0[(2 * u) * 6 + 3 + d]     = lo;
                r0[(2 * u + 1) * 6 + 3 + d] = hi;
            }
        }
    }
    __syncthreads();
    if (ph == 0) {
        const float* r0 = red + h * 49;
        #pragma unroll
        for (int u = 0; u < 4; u++) {
            float L[2][3], R[2][3];
            #pragma unroll
            for (int d = 0; d < 3; d++) {
                UNPK2(L[0][d], L[1][d], acc2L[u][d]);
                UNPK2(R[0][d], R[1][d], acc2R[u][d]);
            }
            #pragma unroll
            for (int e = 0; e < 2; e++) {
                int tt = 2 * u + e;
                float L0 = L[e][0] + r0[tt * 6 + 0];
                float L1 = L[e][1] + r0[tt * 6 + 1];
                float L2 = L[e][2] + r0[tt * 6 + 2];
                float R0 = R[e][0] + r0[tt * 6 + 3];
                float R1 = R[e][1] + r0[tt * 6 + 4];
                float R2 = R[e][2] + r0[tt * 6 + 5];
                float att = fmaf(L0, R0, fmaf(L1, R1, L2 * R2)) + 1e-5f;
                g_att[(size_t)(bg0 + tt) * Hn + h] = att;
            }
        }
    }
}

// ---------- kernel 4a: partial logsumexp ----------
__global__ void __launch_bounds__(128)
lse_partial_kernel() {
    int b  = blockIdx.y;
    int ch = blockIdx.x;
    int h  = threadIdx.x;
    const int GPC = Gn / LSE_CH;
    const float* base = g_att + ((size_t)b * Gn + ch * GPC) * Hn + h;

    float v[GPC];
    #pragma unroll
    for (int i = 0; i < GPC; i++) v[i] = base[(size_t)i * Hn];

    float mx = v[0];
    #pragma unroll
    for (int i = 1; i < GPC; i++) mx = fmaxf(mx, v[i]);
    float s = 0.f;
    #pragma unroll
    for (int i = 0; i < GPC; i++) s += __expf(v[i] - mx);

    g_lsem[(b * LSE_CH + ch) * Hn + h] = mx;
    g_lses[(b * LSE_CH + ch) * Hn + h] = s;
}

// ---------- kernel 4b: combine + MLP ----------
__global__ void __launch_bounds__(128)
finalize_kernel(const float* __restrict__ fc1w, const float* __restrict__ fc1b,
                const float* __restrict__ fc2w, const float* __restrict__ fc2b,
                float* __restrict__ out) {
    int b = blockIdx.x;
    int h = threadIdx.x;

    float M = -3.4e38f;
    #pragma unroll
    for (int ch = 0; ch < LSE_CH; ch++)
        M = fmaxf(M, g_lsem[(b * LSE_CH + ch) * Hn + h]);
    float S = 0.f;
    #pragma unroll
    for (int ch = 0; ch < LSE_CH; ch++) {
        float m = g_lsem[(b * LSE_CH + ch) * Hn + h];
        float s = g_lses[(b * LSE_CH + ch) * Hn + h];
        S += s * __expf(m - M);
    }
    float pooled = M + logf(S);

    __shared__ float ps[Hn];
    __shared__ float red[Hn];
    ps[h] = pooled;
    __syncthreads();

    float a = fc1b[h];
    #pragma unroll 8
    for (int i = 0; i < Hn; i++) a = fmaf(fc1w[h * Hn + i], ps[i], a);
    float hv = a / (1.f + __expf(-a));

    red[h] = hv * fc2w[h];
    __syncthreads();
    for (int st = 64; st > 0; st >>= 1) {
        if (h < st) red[h] += red[h + st];
        __syncthreads();
    }
    if (h == 0) out[b] = red[0] + fc2b[0];
}

// -------------------- launcher --------------------
extern "C" void kernel_launch(void* const* d_in, const int* in_sizes, int n_in,
                              void* d_out, int out_size) {
    const float* x    = (const float*)d_in[0];
    const float* Wmap = (const float*)d_in[1];
    const float* WL   = (const float*)d_in[2];
    const float* WR   = (const float*)d_in[3];
    const float* fc1w = (const float*)d_in[4];
    const float* fc1b = (const float*)d_in[5];
    const float* fc2w = (const float*)d_in[6];
    const float* fc2b = (const float*)d_in[7];
    float* out = (float*)d_out;

    double mu0  = exp(-5.0);
    double dm   = (1.0 - mu0) / 49.0;
    double beta = pow(2.0 / 50.0 * (1.0 - mu0), -2.0);

    const int smem_xc   = Nn * 24 * (int)sizeof(float);
    const int smem_main = (NPAIR * KROW + NPAIR * 24 + Tn * 24) * (int)sizeof(float);

    cudaFuncSetAttribute(xc_kernel, cudaFuncAttributeMaxDynamicSharedMemorySize, smem_xc);
    cudaFuncSetAttribute(main_kernel, cudaFuncAttributeMaxDynamicSharedMemorySize, smem_main);

    pad_weights_kernel<<<NPAIR * QCH, 128>>>(WL, WR);
    xc_kernel<<<(Gn * Mn) / XC_ROWS, XC_ROWS * 24, smem_xc>>>(x, Wmap);
    main_kernel<<<(Bn * Gn) / Tn, 256, smem_main>>>((float)mu0, (float)dm, (float)beta);
    lse_partial_kernel<<<dim3(LSE_CH, Bn), 128>>>();
    finalize_kernel<<<Bn, 128>>>(fc1w, fc1b, fc2w, fc2b, out);
}